// round 10
// baseline (speedup 1.0000x reference)
#include <cuda_runtime.h>
#include <cuda_bf16.h>
#include <cstdint>

#define NCLS   5000
#define NV4    1250          // 5000 / 4
#define LVLS   4
#define NB     4096
#define NROWS  (NB * LVLS)   // 16384
#define BLK    256
#define GRID1  740           // 148 SMs * 5 blocks — exactly one wave
#define BASE_R 22            // 740*22 = 16280; first 104 blocks take 23 rows
#define XTRA_B 104           // 104*23 + 636*22 = 16384
#define MAXR   23
#define ROWB   20000u        // bytes per row (5000 fp32)
#define FBLKS  16

#define L2E    1.4426950408889634f   // log2(e)
#define LN2    0.6931471805599453f

// Scratch (device globals — no allocations, no host API lookups, no atomics)
__device__ int   g_argmax[NROWS];
__device__ float g_ce[NROWS];
__device__ float g_part_ce[FBLKS][3];
__device__ int   g_part_cnt[FBLKS][3];

__device__ __forceinline__ float ex2(float x) {
    float y;
    asm("ex2.approx.ftz.f32 %0, %1;" : "=f"(y) : "f"(x));
    return y;
}
__device__ __forceinline__ unsigned smem_u32(const void* p) {
    return (unsigned)__cvta_generic_to_shared(p);
}
__device__ __forceinline__ void mbar_init(unsigned a) {
    asm volatile("mbarrier.init.shared.b64 [%0], %1;" :: "r"(a), "r"(1u) : "memory");
}
__device__ __forceinline__ void mbar_expect_tx(unsigned a, unsigned bytes) {
    asm volatile("mbarrier.arrive.expect_tx.shared.b64 _, [%0], %1;"
                 :: "r"(a), "r"(bytes) : "memory");
}
__device__ __forceinline__ void bulk_g2s(unsigned dst, const void* src,
                                         unsigned bytes, unsigned mbar) {
    asm volatile(
        "cp.async.bulk.shared::cluster.global.mbarrier::complete_tx::bytes "
        "[%0], [%1], %2, [%3];"
        :: "r"(dst), "l"(src), "r"(bytes), "r"(mbar) : "memory");
}
__device__ __forceinline__ void mbar_wait(unsigned a, unsigned parity) {
    asm volatile(
        "{\n\t"
        ".reg .pred P1;\n\t"
        "WAIT_%=:\n\t"
        "mbarrier.try_wait.parity.acquire.cta.shared::cta.b64 P1, [%0], %1, 0x989680;\n\t"
        "@P1 bra DONE_%=;\n\t"
        "bra WAIT_%=;\n\t"
        "DONE_%=:\n\t"
        "}"
        :: "r"(a), "r"(parity) : "memory");
}
__device__ __forceinline__ void fence_async() {
    asm volatile("fence.proxy.async.shared::cta;" ::: "memory");
}

// ---------------------------------------------------------------------------
// Kernel 1: one-wave persistent row-stats with a 2-stage cp.async.bulk ring.
// TMA engine keeps 20KB/row in flight independent of warp math; consumers
// pull the staged row into registers (LDS) and run the proven R7 math.
// ---------------------------------------------------------------------------
__global__ __launch_bounds__(BLK, 5)
void row_stats_kernel(const float* __restrict__ y_pred,
                      const int*   __restrict__ y_true)
{
    __shared__ __align__(128) float4 stage[2][1280];   // 2 x 20480 B
    __shared__ __align__(8) unsigned long long mbar_store[2];
    __shared__ float sh_xt[MAXR];
    __shared__ float sh_m[8];
    __shared__ float sh_s[8];
    __shared__ float sh_M, sh_S;
    __shared__ int   sh_idx[8];

    const int tid  = threadIdx.x;
    const int bid  = blockIdx.x;
    const int wid  = tid >> 5, lane = tid & 31;
    const unsigned full = 0xffffffffu;

    const int cnt   = BASE_R + (bid < XTRA_B ? 1 : 0);
    const int start = bid * BASE_R + min(bid, XTRA_B);

    const unsigned mb0 = smem_u32(&mbar_store[0]);
    const unsigned mb1 = smem_u32(&mbar_store[1]);
    const unsigned st0 = smem_u32(&stage[0][0]);
    const unsigned st1 = smem_u32(&stage[1][0]);

    // Resolve all target logits for this block's rows up front.
    if (tid < cnt) {
        int row = start + tid;
        int t = __ldg(y_true + row);
        sh_xt[tid] = __ldg(y_pred + (size_t)row * NCLS + t);
    }

    if (tid == 0) { mbar_init(mb0); mbar_init(mb1); }
    __syncthreads();   // barriers + sh_xt visible

    // Prime the 2-stage ring.
    if (tid == 0) {
        mbar_expect_tx(mb0, ROWB);
        bulk_g2s(st0, y_pred + (size_t)start * NCLS, ROWB, mb0);
        mbar_expect_tx(mb1, ROWB);
        bulk_g2s(st1, y_pred + (size_t)(start + 1) * NCLS, ROWB, mb1);
    }

    for (int k = 0; k < cnt; ++k) {
        const int row = start + k;
        const int stg = k & 1;
        const unsigned parity = (unsigned)((k >> 1) & 1);
        const unsigned mb = stg ? mb1 : mb0;
        const unsigned sb = stg ? st1 : st0;
        const float4* sp = stg ? &stage[1][0] : &stage[0][0];

        mbar_wait(mb, parity);

        // ---- pull staged row into registers (conflict-free LDS.128) ----
        float4 v[5];
        #pragma unroll
        for (int it = 0; it < 5; ++it) {
            int i = tid + it * BLK;
            if (it < 4 || i < NV4) v[it] = sp[i];
            else v[it] = make_float4(-1e30f, -1e30f, -1e30f, -1e30f);
        }
        __syncthreads();   // all threads done reading this stage

        // ---- refill this stage with row k+2 (overlaps the math below) ----
        if (tid == 0 && k + 2 < cnt) {
            fence_async();
            mbar_expect_tx(mb, ROWB);
            bulk_g2s(sb, y_pred + (size_t)(row + 2) * NCLS, ROWB, mb);
        }

        // ==== identical math to the proven R7 kernel ====
        float mloc = fmaxf(fmaxf(v[0].x, v[0].y), fmaxf(v[0].z, v[0].w));
        #pragma unroll
        for (int it = 1; it < 5; ++it)
            mloc = fmaxf(mloc, fmaxf(fmaxf(v[it].x, v[it].y),
                                     fmaxf(v[it].z, v[it].w)));

        const float ml = mloc * L2E;
        float s0 = 0.f, s1 = 0.f, s2 = 0.f, s3 = 0.f;
        #pragma unroll
        for (int it = 0; it < 5; ++it) {
            s0 += ex2(fmaf(v[it].x, L2E, -ml));
            s1 += ex2(fmaf(v[it].y, L2E, -ml));
            s2 += ex2(fmaf(v[it].z, L2E, -ml));
            s3 += ex2(fmaf(v[it].w, L2E, -ml));
        }
        float s = (s0 + s1) + (s2 + s3);
        float m = mloc;

        #pragma unroll
        for (int off = 16; off; off >>= 1) {
            float om = __shfl_down_sync(full, m, off);
            float os = __shfl_down_sync(full, s, off);
            float nm = fmaxf(m, om);
            s = s * ex2((m - nm) * L2E) + os * ex2((om - nm) * L2E);
            m = nm;
        }
        if (lane == 0) { sh_m[wid] = m; sh_s[wid] = s; }
        __syncthreads();

        if (wid == 0) {
            m = (lane < 8) ? sh_m[lane] : -1e30f;
            s = (lane < 8) ? sh_s[lane] : 0.0f;
            #pragma unroll
            for (int off = 4; off; off >>= 1) {
                float om = __shfl_down_sync(full, m, off);
                float os = __shfl_down_sync(full, s, off);
                float nm = fmaxf(m, om);
                s = s * ex2((m - nm) * L2E) + os * ex2((om - nm) * L2E);
                m = nm;
            }
            if (lane == 0) { sh_M = m; sh_S = s; }
        }
        __syncthreads();

        // ---- argmax: equality rescan (signed INT_MAX sentinel — R6 lesson) ----
        const float M = sh_M;
        int idx = 0x7fffffff;
        if (mloc == M) {
            #pragma unroll
            for (int it = 0; it < 5; ++it) {
                int gi = (tid + it * BLK) << 2;
                if (v[it].x == M) idx = min(idx, gi + 0);
                if (v[it].y == M) idx = min(idx, gi + 1);
                if (v[it].z == M) idx = min(idx, gi + 2);
                if (v[it].w == M) idx = min(idx, gi + 3);
            }
        }
        idx = __reduce_min_sync(full, idx);
        if (lane == 0) sh_idx[wid] = idx;
        __syncthreads();

        if (tid == 0) {
            int best = sh_idx[0];
            #pragma unroll
            for (int w = 1; w < 8; ++w) best = min(best, sh_idx[w]);
            g_argmax[row] = best;
            g_ce[row] = fmaf(LN2, __log2f(sh_S), sh_M) - sh_xt[k];
        }
    }
}

// ---------------------------------------------------------------------------
// Kernel 2: gather + per-block partial reduce. 16 blocks x 256 threads.
// ---------------------------------------------------------------------------
__global__ __launch_bounds__(BLK)
void gather_kernel(const float* __restrict__ H)
{
    const int tid  = threadIdx.x;
    const int b    = blockIdx.x * BLK + tid;   // 0..4095
    const int base = b * LVLS;

    int i0 = g_argmax[base + 0];
    int i1 = g_argmax[base + 1];
    int i2 = g_argmax[base + 2];
    int i3 = g_argmax[base + 3];
    float ce1 = g_ce[base + 1];
    float ce2 = g_ce[base + 2];
    float ce3 = g_ce[base + 3];
    int c1 = (__ldg(H + (size_t)i0 * NCLS + i1) != 1.0f);
    int c2 = (__ldg(H + (size_t)i1 * NCLS + i2) != 1.0f);
    int c3 = (__ldg(H + (size_t)i2 * NCLS + i3) != 1.0f);

    const unsigned full = 0xffffffffu;
    #pragma unroll
    for (int off = 16; off; off >>= 1) {
        ce1 += __shfl_down_sync(full, ce1, off);
        ce2 += __shfl_down_sync(full, ce2, off);
        ce3 += __shfl_down_sync(full, ce3, off);
    }
    c1 = __reduce_add_sync(full, c1);
    c2 = __reduce_add_sync(full, c2);
    c3 = __reduce_add_sync(full, c3);

    __shared__ float s_ce[3][8];
    __shared__ int   s_c[3][8];
    const int wid = tid >> 5, lane = tid & 31;
    if (lane == 0) {
        s_ce[0][wid] = ce1; s_ce[1][wid] = ce2; s_ce[2][wid] = ce3;
        s_c[0][wid]  = c1;  s_c[1][wid]  = c2;  s_c[2][wid]  = c3;
    }
    __syncthreads();

    if (tid == 0) {
        float a1 = 0.f, a2 = 0.f, a3 = 0.f;
        int   b1 = 0, b2 = 0, b3 = 0;
        #pragma unroll
        for (int w = 0; w < 8; ++w) {
            a1 += s_ce[0][w]; a2 += s_ce[1][w]; a3 += s_ce[2][w];
            b1 += s_c[0][w];  b2 += s_c[1][w];  b3 += s_c[2][w];
        }
        g_part_ce[blockIdx.x][0]  = a1;
        g_part_ce[blockIdx.x][1]  = a2;
        g_part_ce[blockIdx.x][2]  = a3;
        g_part_cnt[blockIdx.x][0] = b1;
        g_part_cnt[blockIdx.x][1] = b2;
        g_part_cnt[blockIdx.x][2] = b3;
    }
}

// ---------------------------------------------------------------------------
// Kernel 3: tiny finalize — one warp sums the 16 partials, writes the scalar.
// ---------------------------------------------------------------------------
__global__ __launch_bounds__(32)
void finalize_kernel(float* __restrict__ out)
{
    const int lane = threadIdx.x;
    float ce1 = 0.f, ce2 = 0.f, ce3 = 0.f;
    int   c1 = 0, c2 = 0, c3 = 0;
    if (lane < FBLKS) {
        ce1 = g_part_ce[lane][0];
        ce2 = g_part_ce[lane][1];
        ce3 = g_part_ce[lane][2];
        c1  = g_part_cnt[lane][0];
        c2  = g_part_cnt[lane][1];
        c3  = g_part_cnt[lane][2];
    }
    const unsigned full = 0xffffffffu;
    #pragma unroll
    for (int off = 8; off; off >>= 1) {
        ce1 += __shfl_down_sync(full, ce1, off);
        ce2 += __shfl_down_sync(full, ce2, off);
        ce3 += __shfl_down_sync(full, ce3, off);
        c1  += __shfl_down_sync(full, c1,  off);
        c2  += __shfl_down_sync(full, c2,  off);
        c3  += __shfl_down_sync(full, c3,  off);
    }
    if (lane == 0) {
        const float E  = 2.718281828459045f;
        const float iB = 1.0f / (float)NB;
        float loss = 0.25f * ((float)c1 * E + ce1 * iB)
                   + 0.15f * ((float)c2 * E + ce2 * iB)
                   + 0.10f * ((float)c3 * E + ce3 * iB);
        out[0] = loss;
    }
}

// ---------------------------------------------------------------------------
extern "C" void kernel_launch(void* const* d_in, const int* in_sizes, int n_in,
                              void* d_out, int out_size)
{
    const float* y_pred = nullptr;
    const int*   y_true = nullptr;
    const float* H      = nullptr;
    for (int i = 0; i < n_in; ++i) {
        if (in_sizes[i] == NROWS * NCLS)      y_pred = (const float*)d_in[i];
        else if (in_sizes[i] == NROWS)        y_true = (const int*)d_in[i];
        else if (in_sizes[i] == NCLS * NCLS)  H      = (const float*)d_in[i];
    }

    row_stats_kernel<<<GRID1, BLK>>>(y_pred, y_true);
    gather_kernel<<<FBLKS, BLK>>>(H);
    finalize_kernel<<<1, 32>>>((float*)d_out);
}

// round 11
// speedup vs baseline: 1.0702x; 1.0702x over previous
#include <cuda_runtime.h>
#include <cuda_bf16.h>
#include <cstdint>

#define NCLS   5000
#define NV4    1250      // 5000 / 4
#define LVLS   4
#define NB     4096
#define NROWS  (NB * LVLS)   // 16384
#define BLK    256
#define RPB    4             // rows per block (software pipeline depth)
#define GRID1  (NROWS / RPB) // 4096
#define FBLKS  16

#define L2E    1.4426950408889634f   // log2(e)
#define LN2    0.6931471805599453f

// Scratch (device globals — no allocations, no host API lookups, no atomics)
__device__ int   g_argmax[NROWS];
__device__ float g_ce[NROWS];
__device__ float g_part_ce[FBLKS][3];
__device__ int   g_part_cnt[FBLKS][3];

__device__ __forceinline__ float ex2(float x) {
    float y;
    asm("ex2.approx.ftz.f32 %0, %1;" : "=f"(y) : "f"(x));
    return y;
}

// ---------------------------------------------------------------------------
// Kernel 1: per-row softmax stats, 4 rows per block, register double-buffered.
// EXACTLY the proven R7 kernel except: 2 barriers per row instead of 3 —
// all warps redundantly combine the 8 warp-partials via shuffles, removing
// the warp0-combine + broadcast barrier.
// ---------------------------------------------------------------------------
__global__ __launch_bounds__(BLK, 4)
void row_stats_kernel(const float* __restrict__ y_pred,
                      const int*   __restrict__ y_true)
{
    const int tid  = threadIdx.x;
    const int row0 = blockIdx.x * RPB;

    __shared__ float sh_xt[RPB];
    __shared__ float sh_m[8];
    __shared__ float sh_s[8];
    __shared__ int   sh_idx[8];

    // Resolve all target logits up front (dependent chain off the critical tail)
    if (tid < RPB) {
        int t = __ldg(y_true + row0 + tid);
        sh_xt[tid] = __ldg(y_pred + (size_t)(row0 + tid) * NCLS + t);
    }

    float4 buf[2][5];

    // Prefetch row 0
    {
        const float4* __restrict__ p =
            reinterpret_cast<const float4*>(y_pred + (size_t)row0 * NCLS);
        #pragma unroll
        for (int it = 0; it < 5; ++it) {
            int i = tid + it * BLK;
            if (it < 4 || i < NV4) buf[0][it] = __ldcs(p + i);
            else buf[0][it] = make_float4(-1e30f, -1e30f, -1e30f, -1e30f);
        }
    }

    const unsigned full = 0xffffffffu;
    const int wid = tid >> 5, lane = tid & 31;

    #pragma unroll
    for (int r = 0; r < RPB; ++r) {
        float4* v = buf[r & 1];

        // ---- prefetch next row (loads fly across the barriers below) ----
        if (r + 1 < RPB) {
            const float4* __restrict__ pn =
                reinterpret_cast<const float4*>(y_pred + (size_t)(row0 + r + 1) * NCLS);
            float4* w = buf[(r + 1) & 1];
            #pragma unroll
            for (int it = 0; it < 5; ++it) {
                int i = tid + it * BLK;
                if (it < 4 || i < NV4) w[it] = __ldcs(pn + i);
                else w[it] = make_float4(-1e30f, -1e30f, -1e30f, -1e30f);
            }
        }

        // ---- Phase A: local max (pure FMNMX tree) ----
        float mloc = fmaxf(fmaxf(v[0].x, v[0].y), fmaxf(v[0].z, v[0].w));
        #pragma unroll
        for (int it = 1; it < 5; ++it)
            mloc = fmaxf(mloc, fmaxf(fmaxf(v[it].x, v[it].y),
                                     fmaxf(v[it].z, v[it].w)));

        // ---- Phase B: sum exp2(x*L2E - ml), 4 accumulators ----
        const float ml = mloc * L2E;
        float s0 = 0.f, s1 = 0.f, s2 = 0.f, s3 = 0.f;
        #pragma unroll
        for (int it = 0; it < 5; ++it) {
            s0 += ex2(fmaf(v[it].x, L2E, -ml));
            s1 += ex2(fmaf(v[it].y, L2E, -ml));
            s2 += ex2(fmaf(v[it].z, L2E, -ml));
            s3 += ex2(fmaf(v[it].w, L2E, -ml));
        }
        float s = (s0 + s1) + (s2 + s3);
        float m = mloc;

        // ---- warp reduce (m, s) ----
        #pragma unroll
        for (int off = 16; off; off >>= 1) {
            float om = __shfl_down_sync(full, m, off);
            float os = __shfl_down_sync(full, s, off);
            float nm = fmaxf(m, om);
            s = s * ex2((m - nm) * L2E) + os * ex2((om - nm) * L2E);
            m = nm;
        }
        if (lane == 0) { sh_m[wid] = m; sh_s[wid] = s; }
        __syncthreads();                                   // barrier 1

        // ---- redundant cross-warp combine in EVERY warp (no 2nd barrier) ----
        float mm = (lane < 8) ? sh_m[lane] : -1e30f;
        float ss = (lane < 8) ? sh_s[lane] : 0.0f;
        #pragma unroll
        for (int off = 4; off; off >>= 1) {
            float om = __shfl_down_sync(full, mm, off);
            float os = __shfl_down_sync(full, ss, off);
            float nm = fmaxf(mm, om);
            ss = ss * ex2((mm - nm) * L2E) + os * ex2((om - nm) * L2E);
            mm = nm;
        }
        const float M = __shfl_sync(full, mm, 0);
        const float S = __shfl_sync(full, ss, 0);

        // ---- argmax: equality rescan (signed INT_MAX sentinel — R6 lesson) ----
        int idx = 0x7fffffff;
        if (mloc == M) {
            #pragma unroll
            for (int it = 0; it < 5; ++it) {
                int gi = (tid + it * BLK) << 2;
                if (v[it].x == M) idx = min(idx, gi + 0);
                if (v[it].y == M) idx = min(idx, gi + 1);
                if (v[it].z == M) idx = min(idx, gi + 2);
                if (v[it].w == M) idx = min(idx, gi + 3);
            }
        }
        idx = __reduce_min_sync(full, idx);
        if (lane == 0) sh_idx[wid] = idx;
        __syncthreads();                                   // barrier 2
        // (also fences sh_m/sh_s for reuse next row)

        if (tid == 0) {
            int best = sh_idx[0];
            #pragma unroll
            for (int w = 1; w < 8; ++w) best = min(best, sh_idx[w]);
            g_argmax[row0 + r] = best;
            g_ce[row0 + r] = fmaf(LN2, __log2f(S), M) - sh_xt[r];
        }
    }
}

// ---------------------------------------------------------------------------
// Kernel 2: gather + per-block partial reduce. 16 blocks x 256 threads.
// ---------------------------------------------------------------------------
__global__ __launch_bounds__(BLK)
void gather_kernel(const float* __restrict__ H)
{
    const int tid  = threadIdx.x;
    const int b    = blockIdx.x * BLK + tid;   // 0..4095
    const int base = b * LVLS;

    int i0 = g_argmax[base + 0];
    int i1 = g_argmax[base + 1];
    int i2 = g_argmax[base + 2];
    int i3 = g_argmax[base + 3];
    float ce1 = g_ce[base + 1];
    float ce2 = g_ce[base + 2];
    float ce3 = g_ce[base + 3];
    int c1 = (__ldg(H + (size_t)i0 * NCLS + i1) != 1.0f);
    int c2 = (__ldg(H + (size_t)i1 * NCLS + i2) != 1.0f);
    int c3 = (__ldg(H + (size_t)i2 * NCLS + i3) != 1.0f);

    const unsigned full = 0xffffffffu;
    #pragma unroll
    for (int off = 16; off; off >>= 1) {
        ce1 += __shfl_down_sync(full, ce1, off);
        ce2 += __shfl_down_sync(full, ce2, off);
        ce3 += __shfl_down_sync(full, ce3, off);
    }
    c1 = __reduce_add_sync(full, c1);
    c2 = __reduce_add_sync(full, c2);
    c3 = __reduce_add_sync(full, c3);

    __shared__ float s_ce[3][8];
    __shared__ int   s_c[3][8];
    const int wid = tid >> 5, lane = tid & 31;
    if (lane == 0) {
        s_ce[0][wid] = ce1; s_ce[1][wid] = ce2; s_ce[2][wid] = ce3;
        s_c[0][wid]  = c1;  s_c[1][wid]  = c2;  s_c[2][wid]  = c3;
    }
    __syncthreads();

    if (tid == 0) {
        float a1 = 0.f, a2 = 0.f, a3 = 0.f;
        int   b1 = 0, b2 = 0, b3 = 0;
        #pragma unroll
        for (int w = 0; w < 8; ++w) {
            a1 += s_ce[0][w]; a2 += s_ce[1][w]; a3 += s_ce[2][w];
            b1 += s_c[0][w];  b2 += s_c[1][w];  b3 += s_c[2][w];
        }
        g_part_ce[blockIdx.x][0]  = a1;
        g_part_ce[blockIdx.x][1]  = a2;
        g_part_ce[blockIdx.x][2]  = a3;
        g_part_cnt[blockIdx.x][0] = b1;
        g_part_cnt[blockIdx.x][1] = b2;
        g_part_cnt[blockIdx.x][2] = b3;
    }
}

// ---------------------------------------------------------------------------
// Kernel 3: tiny finalize — one warp sums the 16 partials, writes the scalar.
// ---------------------------------------------------------------------------
__global__ __launch_bounds__(32)
void finalize_kernel(float* __restrict__ out)
{
    const int lane = threadIdx.x;
    float ce1 = 0.f, ce2 = 0.f, ce3 = 0.f;
    int   c1 = 0, c2 = 0, c3 = 0;
    if (lane < FBLKS) {
        ce1 = g_part_ce[lane][0];
        ce2 = g_part_ce[lane][1];
        ce3 = g_part_ce[lane][2];
        c1  = g_part_cnt[lane][0];
        c2  = g_part_cnt[lane][1];
        c3  = g_part_cnt[lane][2];
    }
    const unsigned full = 0xffffffffu;
    #pragma unroll
    for (int off = 8; off; off >>= 1) {
        ce1 += __shfl_down_sync(full, ce1, off);
        ce2 += __shfl_down_sync(full, ce2, off);
        ce3 += __shfl_down_sync(full, ce3, off);
        c1  += __shfl_down_sync(full, c1,  off);
        c2  += __shfl_down_sync(full, c2,  off);
        c3  += __shfl_down_sync(full, c3,  off);
    }
    if (lane == 0) {
        const float E  = 2.718281828459045f;
        const float iB = 1.0f / (float)NB;
        float loss = 0.25f * ((float)c1 * E + ce1 * iB)
                   + 0.15f * ((float)c2 * E + ce2 * iB)
                   + 0.10f * ((float)c3 * E + ce3 * iB);
        out[0] = loss;
    }
}

// ---------------------------------------------------------------------------
extern "C" void kernel_launch(void* const* d_in, const int* in_sizes, int n_in,
                              void* d_out, int out_size)
{
    const float* y_pred = nullptr;
    const int*   y_true = nullptr;
    const float* H      = nullptr;
    for (int i = 0; i < n_in; ++i) {
        if (in_sizes[i] == NROWS * NCLS)      y_pred = (const float*)d_in[i];
        else if (in_sizes[i] == NROWS)        y_true = (const int*)d_in[i];
        else if (in_sizes[i] == NCLS * NCLS)  H      = (const float*)d_in[i];
    }

    row_stats_kernel<<<GRID1, BLK>>>(y_pred, y_true);
    gather_kernel<<<FBLKS, BLK>>>(H);
    finalize_kernel<<<1, 32>>>((float*)d_out);
}

// round 12
// speedup vs baseline: 1.0958x; 1.0240x over previous
#include <cuda_runtime.h>
#include <cuda_bf16.h>
#include <cstdint>

#define NCLS   5000
#define NV4    1250      // 5000 / 4
#define LVLS   4
#define NB     4096
#define NROWS  (NB * LVLS)   // 16384
#define BLK    256
#define RPB    4             // rows per block (software pipeline depth)
#define GRID1  (NROWS / RPB) // 4096
#define GBLK   128           // gather block size
#define GBLKS  32            // gather blocks (32*128 = 4096 = NB)

#define L2E    1.4426950408889634f   // log2(e)
#define LN2    0.6931471805599453f

// Scratch (device globals — no allocations, no host API lookups, no atomics)
__device__ __align__(16) int   g_argmax[NROWS];
__device__ __align__(16) float g_ce[NROWS];
__device__ float g_part_ce[GBLKS][3];
__device__ int   g_part_cnt[GBLKS][3];

__device__ __forceinline__ float ex2(float x) {
    float y;
    asm("ex2.approx.ftz.f32 %0, %1;" : "=f"(y) : "f"(x));
    return y;
}

// ---------------------------------------------------------------------------
// Kernel 1: per-row softmax stats, 4 rows per block, register double-buffered.
// Byte-exact logic of the measured-best R7 kernel (51.4 us, DRAM 81.3%).
// ---------------------------------------------------------------------------
__global__ __launch_bounds__(BLK, 4)
void row_stats_kernel(const float* __restrict__ y_pred,
                      const int*   __restrict__ y_true)
{
    const int tid  = threadIdx.x;
    const int row0 = blockIdx.x * RPB;

    __shared__ float sh_xt[RPB];
    __shared__ float sh_m[8];
    __shared__ float sh_s[8];
    __shared__ float sh_M, sh_S;
    __shared__ int   sh_idx[8];

    // Resolve all target logits up front (dependent chain off the critical tail)
    if (tid < RPB) {
        int t = __ldg(y_true + row0 + tid);
        sh_xt[tid] = __ldg(y_pred + (size_t)(row0 + tid) * NCLS + t);
    }

    float4 buf[2][5];

    // Prefetch row 0
    {
        const float4* __restrict__ p =
            reinterpret_cast<const float4*>(y_pred + (size_t)row0 * NCLS);
        #pragma unroll
        for (int it = 0; it < 5; ++it) {
            int i = tid + it * BLK;
            if (it < 4 || i < NV4) buf[0][it] = __ldcs(p + i);
            else buf[0][it] = make_float4(-1e30f, -1e30f, -1e30f, -1e30f);
        }
    }

    const unsigned full = 0xffffffffu;
    const int wid = tid >> 5, lane = tid & 31;

    #pragma unroll
    for (int r = 0; r < RPB; ++r) {
        float4* v = buf[r & 1];

        // ---- prefetch next row (loads fly across the barriers below) ----
        if (r + 1 < RPB) {
            const float4* __restrict__ pn =
                reinterpret_cast<const float4*>(y_pred + (size_t)(row0 + r + 1) * NCLS);
            float4* w = buf[(r + 1) & 1];
            #pragma unroll
            for (int it = 0; it < 5; ++it) {
                int i = tid + it * BLK;
                if (it < 4 || i < NV4) w[it] = __ldcs(pn + i);
                else w[it] = make_float4(-1e30f, -1e30f, -1e30f, -1e30f);
            }
        }

        // ---- Phase A: local max (pure FMNMX tree) ----
        float mloc = fmaxf(fmaxf(v[0].x, v[0].y), fmaxf(v[0].z, v[0].w));
        #pragma unroll
        for (int it = 1; it < 5; ++it)
            mloc = fmaxf(mloc, fmaxf(fmaxf(v[it].x, v[it].y),
                                     fmaxf(v[it].z, v[it].w)));

        // ---- Phase B: sum exp2(x*L2E - ml), 4 accumulators ----
        const float ml = mloc * L2E;
        float s0 = 0.f, s1 = 0.f, s2 = 0.f, s3 = 0.f;
        #pragma unroll
        for (int it = 0; it < 5; ++it) {
            s0 += ex2(fmaf(v[it].x, L2E, -ml));
            s1 += ex2(fmaf(v[it].y, L2E, -ml));
            s2 += ex2(fmaf(v[it].z, L2E, -ml));
            s3 += ex2(fmaf(v[it].w, L2E, -ml));
        }
        float s = (s0 + s1) + (s2 + s3);
        float m = mloc;

        // ---- warp reduce (m, s) ----
        #pragma unroll
        for (int off = 16; off; off >>= 1) {
            float om = __shfl_down_sync(full, m, off);
            float os = __shfl_down_sync(full, s, off);
            float nm = fmaxf(m, om);
            s = s * ex2((m - nm) * L2E) + os * ex2((om - nm) * L2E);
            m = nm;
        }
        if (lane == 0) { sh_m[wid] = m; sh_s[wid] = s; }
        __syncthreads();

        if (wid == 0) {
            m = (lane < 8) ? sh_m[lane] : -1e30f;
            s = (lane < 8) ? sh_s[lane] : 0.0f;
            #pragma unroll
            for (int off = 4; off; off >>= 1) {
                float om = __shfl_down_sync(full, m, off);
                float os = __shfl_down_sync(full, s, off);
                float nm = fmaxf(m, om);
                s = s * ex2((m - nm) * L2E) + os * ex2((om - nm) * L2E);
                m = nm;
            }
            if (lane == 0) { sh_M = m; sh_S = s; }
        }
        __syncthreads();

        // ---- argmax: equality rescan (signed INT_MAX sentinel — R6 lesson) ----
        const float M = sh_M;
        int idx = 0x7fffffff;
        if (mloc == M) {
            #pragma unroll
            for (int it = 0; it < 5; ++it) {
                int gi = (tid + it * BLK) << 2;
                if (v[it].x == M) idx = min(idx, gi + 0);
                if (v[it].y == M) idx = min(idx, gi + 1);
                if (v[it].z == M) idx = min(idx, gi + 2);
                if (v[it].w == M) idx = min(idx, gi + 3);
            }
        }
        idx = __reduce_min_sync(full, idx);
        if (lane == 0) sh_idx[wid] = idx;
        __syncthreads();

        if (tid == 0) {
            int best = sh_idx[0];
            #pragma unroll
            for (int w = 1; w < 8; ++w) best = min(best, sh_idx[w]);
            g_argmax[row0 + r] = best;
            g_ce[row0 + r] = fmaf(LN2, __log2f(sh_S), sh_M) - sh_xt[r];
        }
    }
}

// ---------------------------------------------------------------------------
// Kernel 2: gather + per-block partial reduce. 32 blocks x 128 threads,
// one thread per batch element; scratch read as int4/float4.
// ---------------------------------------------------------------------------
__global__ __launch_bounds__(GBLK)
void gather_kernel(const float* __restrict__ H)
{
    const int tid  = threadIdx.x;
    const int b    = blockIdx.x * GBLK + tid;  // 0..4095
    const int base = b * LVLS;                 // multiple of 4 -> 16B aligned

    int4   ia = *reinterpret_cast<const int4*>(g_argmax + base);
    float4 ca = *reinterpret_cast<const float4*>(g_ce + base);

    float ce1 = ca.y, ce2 = ca.z, ce3 = ca.w;
    int c1 = (__ldg(H + (size_t)ia.x * NCLS + ia.y) != 1.0f);
    int c2 = (__ldg(H + (size_t)ia.y * NCLS + ia.z) != 1.0f);
    int c3 = (__ldg(H + (size_t)ia.z * NCLS + ia.w) != 1.0f);

    const unsigned full = 0xffffffffu;
    #pragma unroll
    for (int off = 16; off; off >>= 1) {
        ce1 += __shfl_down_sync(full, ce1, off);
        ce2 += __shfl_down_sync(full, ce2, off);
        ce3 += __shfl_down_sync(full, ce3, off);
    }
    c1 = __reduce_add_sync(full, c1);
    c2 = __reduce_add_sync(full, c2);
    c3 = __reduce_add_sync(full, c3);

    __shared__ float s_ce[3][4];
    __shared__ int   s_c[3][4];
    const int wid = tid >> 5, lane = tid & 31;
    if (lane == 0) {
        s_ce[0][wid] = ce1; s_ce[1][wid] = ce2; s_ce[2][wid] = ce3;
        s_c[0][wid]  = c1;  s_c[1][wid]  = c2;  s_c[2][wid]  = c3;
    }
    __syncthreads();

    if (tid == 0) {
        float a1 = 0.f, a2 = 0.f, a3 = 0.f;
        int   b1 = 0, b2 = 0, b3 = 0;
        #pragma unroll
        for (int w = 0; w < 4; ++w) {
            a1 += s_ce[0][w]; a2 += s_ce[1][w]; a3 += s_ce[2][w];
            b1 += s_c[0][w];  b2 += s_c[1][w];  b3 += s_c[2][w];
        }
        g_part_ce[blockIdx.x][0]  = a1;
        g_part_ce[blockIdx.x][1]  = a2;
        g_part_ce[blockIdx.x][2]  = a3;
        g_part_cnt[blockIdx.x][0] = b1;
        g_part_cnt[blockIdx.x][1] = b2;
        g_part_cnt[blockIdx.x][2] = b3;
    }
}

// ---------------------------------------------------------------------------
// Kernel 3: tiny finalize — one warp sums the 32 partials, writes the scalar.
// ---------------------------------------------------------------------------
__global__ __launch_bounds__(32)
void finalize_kernel(float* __restrict__ out)
{
    const int lane = threadIdx.x;   // 0..31 == GBLKS
    float ce1 = g_part_ce[lane][0];
    float ce2 = g_part_ce[lane][1];
    float ce3 = g_part_ce[lane][2];
    int   c1  = g_part_cnt[lane][0];
    int   c2  = g_part_cnt[lane][1];
    int   c3  = g_part_cnt[lane][2];

    const unsigned full = 0xffffffffu;
    #pragma unroll
    for (int off = 16; off; off >>= 1) {
        ce1 += __shfl_down_sync(full, ce1, off);
        ce2 += __shfl_down_sync(full, ce2, off);
        ce3 += __shfl_down_sync(full, ce3, off);
        c1  += __shfl_down_sync(full, c1,  off);
        c2  += __shfl_down_sync(full, c2,  off);
        c3  += __shfl_down_sync(full, c3,  off);
    }
    if (lane == 0) {
        const float E  = 2.718281828459045f;
        const float iB = 1.0f / (float)NB;
        float loss = 0.25f * ((float)c1 * E + ce1 * iB)
                   + 0.15f * ((float)c2 * E + ce2 * iB)
                   + 0.10f * ((float)c3 * E + ce3 * iB);
        out[0] = loss;
    }
}

// ---------------------------------------------------------------------------
extern "C" void kernel_launch(void* const* d_in, const int* in_sizes, int n_in,
                              void* d_out, int out_size)
{
    const float* y_pred = nullptr;
    const int*   y_true = nullptr;
    const float* H      = nullptr;
    for (int i = 0; i < n_in; ++i) {
        if (in_sizes[i] == NROWS * NCLS)      y_pred = (const float*)d_in[i];
        else if (in_sizes[i] == NROWS)        y_true = (const int*)d_in[i];
        else if (in_sizes[i] == NCLS * NCLS)  H      = (const float*)d_in[i];
    }

    row_stats_kernel<<<GRID1, BLK>>>(y_pred, y_true);
    gather_kernel<<<GBLKS, GBLK>>>(H);
    finalize_kernel<<<1, 32>>>((float*)d_out);
}

// round 13
// speedup vs baseline: 1.0965x; 1.0006x over previous
#include <cuda_runtime.h>
#include <cuda_bf16.h>
#include <cstdint>

#define NCLS   5000
#define NV4    1250      // 5000 / 4
#define LVLS   4
#define NB     4096
#define NROWS  (NB * LVLS)   // 16384
#define BLK    256
#define RPB    4             // rows per block == LVLS: block b == batch item b
#define GRID1  (NROWS / RPB) // 4096

#define L2E    1.4426950408889634f   // log2(e)
#define LN2    0.6931471805599453f

// Scratch: one float2 partial per block {weighted_ce, weighted_count}
__device__ __align__(8) float2 g_part[GRID1];

__device__ __forceinline__ float ex2(float x) {
    float y;
    asm("ex2.approx.ftz.f32 %0, %1;" : "=f"(y) : "f"(x));
    return y;
}

// ---------------------------------------------------------------------------
// Kernel 1: per-batch-item softmax stats + fused H-consistency epilogue.
// Rows 4b..4b+3 are levels 0..3 of batch item b, so the block's own argmaxes
// are sufficient for the H gather; its latency hides behind other blocks'
// streaming. Per-row math byte-identical to the measured-best R7/R12 kernel.
// ---------------------------------------------------------------------------
__global__ __launch_bounds__(BLK, 4)
void row_stats_kernel(const float* __restrict__ y_pred,
                      const int*   __restrict__ y_true,
                      const float* __restrict__ H)
{
    const int tid  = threadIdx.x;
    const int row0 = blockIdx.x * RPB;

    __shared__ float sh_xt[RPB];
    __shared__ float sh_m[8];
    __shared__ float sh_s[8];
    __shared__ float sh_M, sh_S;
    __shared__ int   sh_idx[8];

    // Resolve all target logits up front (dependent chain off the critical tail)
    if (tid < RPB) {
        int t = __ldg(y_true + row0 + tid);
        sh_xt[tid] = __ldg(y_pred + (size_t)(row0 + tid) * NCLS + t);
    }

    float4 buf[2][5];

    // Prefetch row 0
    {
        const float4* __restrict__ p =
            reinterpret_cast<const float4*>(y_pred + (size_t)row0 * NCLS);
        #pragma unroll
        for (int it = 0; it < 5; ++it) {
            int i = tid + it * BLK;
            if (it < 4 || i < NV4) buf[0][it] = __ldcs(p + i);
            else buf[0][it] = make_float4(-1e30f, -1e30f, -1e30f, -1e30f);
        }
    }

    const unsigned full = 0xffffffffu;
    const int wid = tid >> 5, lane = tid & 31;

    int   am[RPB];     // thread 0: per-level argmax (registers, r unrolled)
    float cel[RPB];    // thread 0: per-level cross-entropy

    #pragma unroll
    for (int r = 0; r < RPB; ++r) {
        float4* v = buf[r & 1];

        // ---- prefetch next row (loads fly across the barriers below) ----
        if (r + 1 < RPB) {
            const float4* __restrict__ pn =
                reinterpret_cast<const float4*>(y_pred + (size_t)(row0 + r + 1) * NCLS);
            float4* w = buf[(r + 1) & 1];
            #pragma unroll
            for (int it = 0; it < 5; ++it) {
                int i = tid + it * BLK;
                if (it < 4 || i < NV4) w[it] = __ldcs(pn + i);
                else w[it] = make_float4(-1e30f, -1e30f, -1e30f, -1e30f);
            }
        }

        // ---- Phase A: local max (pure FMNMX tree) ----
        float mloc = fmaxf(fmaxf(v[0].x, v[0].y), fmaxf(v[0].z, v[0].w));
        #pragma unroll
        for (int it = 1; it < 5; ++it)
            mloc = fmaxf(mloc, fmaxf(fmaxf(v[it].x, v[it].y),
                                     fmaxf(v[it].z, v[it].w)));

        // ---- Phase B: sum exp2(x*L2E - ml), 4 accumulators ----
        const float ml = mloc * L2E;
        float s0 = 0.f, s1 = 0.f, s2 = 0.f, s3 = 0.f;
        #pragma unroll
        for (int it = 0; it < 5; ++it) {
            s0 += ex2(fmaf(v[it].x, L2E, -ml));
            s1 += ex2(fmaf(v[it].y, L2E, -ml));
            s2 += ex2(fmaf(v[it].z, L2E, -ml));
            s3 += ex2(fmaf(v[it].w, L2E, -ml));
        }
        float s = (s0 + s1) + (s2 + s3);
        float m = mloc;

        // ---- warp reduce (m, s) ----
        #pragma unroll
        for (int off = 16; off; off >>= 1) {
            float om = __shfl_down_sync(full, m, off);
            float os = __shfl_down_sync(full, s, off);
            float nm = fmaxf(m, om);
            s = s * ex2((m - nm) * L2E) + os * ex2((om - nm) * L2E);
            m = nm;
        }
        if (lane == 0) { sh_m[wid] = m; sh_s[wid] = s; }
        __syncthreads();

        if (wid == 0) {
            m = (lane < 8) ? sh_m[lane] : -1e30f;
            s = (lane < 8) ? sh_s[lane] : 0.0f;
            #pragma unroll
            for (int off = 4; off; off >>= 1) {
                float om = __shfl_down_sync(full, m, off);
                float os = __shfl_down_sync(full, s, off);
                float nm = fmaxf(m, om);
                s = s * ex2((m - nm) * L2E) + os * ex2((om - nm) * L2E);
                m = nm;
            }
            if (lane == 0) { sh_M = m; sh_S = s; }
        }
        __syncthreads();

        // ---- argmax: equality rescan (signed INT_MAX sentinel — R6 lesson) ----
        const float M = sh_M;
        int idx = 0x7fffffff;
        if (mloc == M) {
            #pragma unroll
            for (int it = 0; it < 5; ++it) {
                int gi = (tid + it * BLK) << 2;
                if (v[it].x == M) idx = min(idx, gi + 0);
                if (v[it].y == M) idx = min(idx, gi + 1);
                if (v[it].z == M) idx = min(idx, gi + 2);
                if (v[it].w == M) idx = min(idx, gi + 3);
            }
        }
        idx = __reduce_min_sync(full, idx);
        if (lane == 0) sh_idx[wid] = idx;
        __syncthreads();

        if (tid == 0) {
            int best = sh_idx[0];
            #pragma unroll
            for (int w = 1; w < 8; ++w) best = min(best, sh_idx[w]);
            am[r]  = best;
            cel[r] = fmaf(LN2, __log2f(sh_S), sh_M) - sh_xt[r];
        }
    }

    // ---- fused epilogue: H consistency probes for this batch item ----
    if (tid == 0) {
        float h1 = __ldg(H + (size_t)am[0] * NCLS + am[1]);
        float h2 = __ldg(H + (size_t)am[1] * NCLS + am[2]);
        float h3 = __ldg(H + (size_t)am[2] * NCLS + am[3]);
        float c1 = (h1 != 1.0f) ? 1.0f : 0.0f;
        float c2 = (h2 != 1.0f) ? 1.0f : 0.0f;
        float c3 = (h3 != 1.0f) ? 1.0f : 0.0f;
        float pcw = 0.25f * c1 + 0.15f * c2 + 0.10f * c3;
        float pce = 0.25f * cel[1] + 0.15f * cel[2] + 0.10f * cel[3];
        g_part[blockIdx.x] = make_float2(pce, pcw);
    }
}

// ---------------------------------------------------------------------------
// Kernel 2: deterministic reduction of 4096 float2 partials -> scalar loss.
// One block, 256 threads, 16 partials each (fixed order), tree reduce.
// ---------------------------------------------------------------------------
__global__ __launch_bounds__(BLK)
void final_reduce_kernel(float* __restrict__ out)
{
    const int tid = threadIdx.x;
    float ace = 0.f, acw = 0.f;
    #pragma unroll
    for (int k = 0; k < 16; ++k) {
        float2 p = g_part[tid + k * BLK];
        ace += p.x;
        acw += p.y;
    }

    const unsigned full = 0xffffffffu;
    #pragma unroll
    for (int off = 16; off; off >>= 1) {
        ace += __shfl_down_sync(full, ace, off);
        acw += __shfl_down_sync(full, acw, off);
    }

    __shared__ float s_ce[8], s_cw[8];
    const int wid = tid >> 5, lane = tid & 31;
    if (lane == 0) { s_ce[wid] = ace; s_cw[wid] = acw; }
    __syncthreads();

    if (tid == 0) {
        float tce = s_ce[0], tcw = s_cw[0];
        #pragma unroll
        for (int w = 1; w < 8; ++w) { tce += s_ce[w]; tcw += s_cw[w]; }
        const float E  = 2.718281828459045f;
        const float iB = 1.0f / (float)NB;
        out[0] = E * tcw + tce * iB;
    }
}

// ---------------------------------------------------------------------------
extern "C" void kernel_launch(void* const* d_in, const int* in_sizes, int n_in,
                              void* d_out, int out_size)
{
    const float* y_pred = nullptr;
    const int*   y_true = nullptr;
    const float* H      = nullptr;
    for (int i = 0; i < n_in; ++i) {
        if (in_sizes[i] == NROWS * NCLS)      y_pred = (const float*)d_in[i];
        else if (in_sizes[i] == NROWS)        y_true = (const int*)d_in[i];
        else if (in_sizes[i] == NCLS * NCLS)  H      = (const float*)d_in[i];
    }

    row_stats_kernel<<<GRID1, BLK>>>(y_pred, y_true, H);
    final_reduce_kernel<<<1, BLK>>>((float*)d_out);
}

// round 14
// speedup vs baseline: 1.1021x; 1.0052x over previous
#include <cuda_runtime.h>
#include <cuda_bf16.h>
#include <cstdint>

#define NCLS   5000
#define NV4    1250      // 5000 / 4
#define LVLS   4
#define NB     4096
#define NROWS  (NB * LVLS)   // 16384
#define BLK    256
#define RPB    4             // rows per block == LVLS: block b == batch item b
#define GRID1  (NROWS / RPB) // 4096

#define L2E    1.4426950408889634f   // log2(e)
#define LN2    0.6931471805599453f

// Scratch: one float2 partial per block {weighted_ce, weighted_count}
__device__ __align__(16) float2 g_part[GRID1];

__device__ __forceinline__ float ex2(float x) {
    float y;
    asm("ex2.approx.ftz.f32 %0, %1;" : "=f"(y) : "f"(x));
    return y;
}

// ---------------------------------------------------------------------------
// Kernel 1: per-batch-item softmax stats + fused H-consistency epilogue.
// Byte-identical to the R13 kernel (row_stats converged: ~51 us, 82% DRAM).
// ---------------------------------------------------------------------------
__global__ __launch_bounds__(BLK, 4)
void row_stats_kernel(const float* __restrict__ y_pred,
                      const int*   __restrict__ y_true,
                      const float* __restrict__ H)
{
    const int tid  = threadIdx.x;
    const int row0 = blockIdx.x * RPB;

    __shared__ float sh_xt[RPB];
    __shared__ float sh_m[8];
    __shared__ float sh_s[8];
    __shared__ float sh_M, sh_S;
    __shared__ int   sh_idx[8];

    // Resolve all target logits up front (dependent chain off the critical tail)
    if (tid < RPB) {
        int t = __ldg(y_true + row0 + tid);
        sh_xt[tid] = __ldg(y_pred + (size_t)(row0 + tid) * NCLS + t);
    }

    float4 buf[2][5];

    // Prefetch row 0
    {
        const float4* __restrict__ p =
            reinterpret_cast<const float4*>(y_pred + (size_t)row0 * NCLS);
        #pragma unroll
        for (int it = 0; it < 5; ++it) {
            int i = tid + it * BLK;
            if (it < 4 || i < NV4) buf[0][it] = __ldcs(p + i);
            else buf[0][it] = make_float4(-1e30f, -1e30f, -1e30f, -1e30f);
        }
    }

    const unsigned full = 0xffffffffu;
    const int wid = tid >> 5, lane = tid & 31;

    int   am[RPB];     // thread 0: per-level argmax (registers, r unrolled)
    float cel[RPB];    // thread 0: per-level cross-entropy

    #pragma unroll
    for (int r = 0; r < RPB; ++r) {
        float4* v = buf[r & 1];

        // ---- prefetch next row (loads fly across the barriers below) ----
        if (r + 1 < RPB) {
            const float4* __restrict__ pn =
                reinterpret_cast<const float4*>(y_pred + (size_t)(row0 + r + 1) * NCLS);
            float4* w = buf[(r + 1) & 1];
            #pragma unroll
            for (int it = 0; it < 5; ++it) {
                int i = tid + it * BLK;
                if (it < 4 || i < NV4) w[it] = __ldcs(pn + i);
                else w[it] = make_float4(-1e30f, -1e30f, -1e30f, -1e30f);
            }
        }

        // ---- Phase A: local max (pure FMNMX tree) ----
        float mloc = fmaxf(fmaxf(v[0].x, v[0].y), fmaxf(v[0].z, v[0].w));
        #pragma unroll
        for (int it = 1; it < 5; ++it)
            mloc = fmaxf(mloc, fmaxf(fmaxf(v[it].x, v[it].y),
                                     fmaxf(v[it].z, v[it].w)));

        // ---- Phase B: sum exp2(x*L2E - ml), 4 accumulators ----
        const float ml = mloc * L2E;
        float s0 = 0.f, s1 = 0.f, s2 = 0.f, s3 = 0.f;
        #pragma unroll
        for (int it = 0; it < 5; ++it) {
            s0 += ex2(fmaf(v[it].x, L2E, -ml));
            s1 += ex2(fmaf(v[it].y, L2E, -ml));
            s2 += ex2(fmaf(v[it].z, L2E, -ml));
            s3 += ex2(fmaf(v[it].w, L2E, -ml));
        }
        float s = (s0 + s1) + (s2 + s3);
        float m = mloc;

        // ---- warp reduce (m, s) ----
        #pragma unroll
        for (int off = 16; off; off >>= 1) {
            float om = __shfl_down_sync(full, m, off);
            float os = __shfl_down_sync(full, s, off);
            float nm = fmaxf(m, om);
            s = s * ex2((m - nm) * L2E) + os * ex2((om - nm) * L2E);
            m = nm;
        }
        if (lane == 0) { sh_m[wid] = m; sh_s[wid] = s; }
        __syncthreads();

        if (wid == 0) {
            m = (lane < 8) ? sh_m[lane] : -1e30f;
            s = (lane < 8) ? sh_s[lane] : 0.0f;
            #pragma unroll
            for (int off = 4; off; off >>= 1) {
                float om = __shfl_down_sync(full, m, off);
                float os = __shfl_down_sync(full, s, off);
                float nm = fmaxf(m, om);
                s = s * ex2((m - nm) * L2E) + os * ex2((om - nm) * L2E);
                m = nm;
            }
            if (lane == 0) { sh_M = m; sh_S = s; }
        }
        __syncthreads();

        // ---- argmax: equality rescan (signed INT_MAX sentinel — R6 lesson) ----
        const float M = sh_M;
        int idx = 0x7fffffff;
        if (mloc == M) {
            #pragma unroll
            for (int it = 0; it < 5; ++it) {
                int gi = (tid + it * BLK) << 2;
                if (v[it].x == M) idx = min(idx, gi + 0);
                if (v[it].y == M) idx = min(idx, gi + 1);
                if (v[it].z == M) idx = min(idx, gi + 2);
                if (v[it].w == M) idx = min(idx, gi + 3);
            }
        }
        idx = __reduce_min_sync(full, idx);
        if (lane == 0) sh_idx[wid] = idx;
        __syncthreads();

        if (tid == 0) {
            int best = sh_idx[0];
            #pragma unroll
            for (int w = 1; w < 8; ++w) best = min(best, sh_idx[w]);
            am[r]  = best;
            cel[r] = fmaf(LN2, __log2f(sh_S), sh_M) - sh_xt[r];
        }
    }

    // ---- fused epilogue: H consistency probes for this batch item ----
    if (tid == 0) {
        float h1 = __ldg(H + (size_t)am[0] * NCLS + am[1]);
        float h2 = __ldg(H + (size_t)am[1] * NCLS + am[2]);
        float h3 = __ldg(H + (size_t)am[2] * NCLS + am[3]);
        float c1 = (h1 != 1.0f) ? 1.0f : 0.0f;
        float c2 = (h2 != 1.0f) ? 1.0f : 0.0f;
        float c3 = (h3 != 1.0f) ? 1.0f : 0.0f;
        float pcw = 0.25f * c1 + 0.15f * c2 + 0.10f * c3;
        float pce = 0.25f * cel[1] + 0.15f * cel[2] + 0.10f * cel[3];
        g_part[blockIdx.x] = make_float2(pce, pcw);
    }
}

// ---------------------------------------------------------------------------
// Kernel 2: deterministic reduction of 4096 float2 partials -> scalar loss.
// 1024 threads, 2 x LDG.128 each (2048 float4 total), fixed-order tree.
// ---------------------------------------------------------------------------
__global__ __launch_bounds__(1024)
void final_reduce_kernel(float* __restrict__ out)
{
    const int tid = threadIdx.x;
    const float4* __restrict__ gp4 = reinterpret_cast<const float4*>(g_part);

    // 2048 float4 total; thread t takes gp4[t] and gp4[t + 1024].
    float4 a = gp4[tid];
    float4 b = gp4[tid + 1024];
    float ace = (a.x + a.z) + (b.x + b.z);   // .x/.z = pce of two partials
    float acw = (a.y + a.w) + (b.y + b.w);   // .y/.w = pcw of two partials

    const unsigned full = 0xffffffffu;
    #pragma unroll
    for (int off = 16; off; off >>= 1) {
        ace += __shfl_down_sync(full, ace, off);
        acw += __shfl_down_sync(full, acw, off);
    }

    __shared__ float s_ce[32], s_cw[32];
    const int wid = tid >> 5, lane = tid & 31;
    if (lane == 0) { s_ce[wid] = ace; s_cw[wid] = acw; }
    __syncthreads();

    if (wid == 0) {
        float tce = s_ce[lane];
        float tcw = s_cw[lane];
        #pragma unroll
        for (int off = 16; off; off >>= 1) {
            tce += __shfl_down_sync(full, tce, off);
            tcw += __shfl_down_sync(full, tcw, off);
        }
        if (lane == 0) {
            const float E  = 2.718281828459045f;
            const float iB = 1.0f / (float)NB;
            out[0] = E * tcw + tce * iB;
        }
    }
}

// ---------------------------------------------------------------------------
extern "C" void kernel_launch(void* const* d_in, const int* in_sizes, int n_in,
                              void* d_out, int out_size)
{
    const float* y_pred = nullptr;
    const int*   y_true = nullptr;
    const float* H      = nullptr;
    for (int i = 0; i < n_in; ++i) {
        if (in_sizes[i] == NROWS * NCLS)      y_pred = (const float*)d_in[i];
        else if (in_sizes[i] == NROWS)        y_true = (const int*)d_in[i];
        else if (in_sizes[i] == NCLS * NCLS)  H      = (const float*)d_in[i];
    }

    row_stats_kernel<<<GRID1, BLK>>>(y_pred, y_true, H);
    final_reduce_kernel<<<1, 1024>>>((float*)d_out);
}

// round 15
// speedup vs baseline: 1.1156x; 1.0122x over previous
#include <cuda_runtime.h>
#include <cuda_bf16.h>
#include <cstdint>

#define NCLS   5000
#define NV4    1250      // 5000 / 4
#define LVLS   4
#define NB     4096
#define NROWS  (NB * LVLS)   // 16384
#define BLK    256
#define RPB    4             // rows per block == LVLS: block b == batch item b
#define GRID1  (NROWS / RPB) // 4096

#define L2E    1.4426950408889634f   // log2(e)
#define LN2    0.6931471805599453f

// Scratch: one float2 partial per block {weighted_ce, weighted_count}
__device__ __align__(16) float2 g_part[GRID1];

__device__ __forceinline__ float ex2(float x) {
    float y;
    asm("ex2.approx.ftz.f32 %0, %1;" : "=f"(y) : "f"(x));
    return y;
}

// ---------------------------------------------------------------------------
// Kernel 1: per-batch-item softmax stats + fused H-consistency epilogue.
// Byte-identical math to the converged R13/R14 kernel (~51 us, 82% DRAM);
// adds only the PDL completion trigger after the partial store.
// ---------------------------------------------------------------------------
__global__ __launch_bounds__(BLK, 4)
void row_stats_kernel(const float* __restrict__ y_pred,
                      const int*   __restrict__ y_true,
                      const float* __restrict__ H)
{
    const int tid  = threadIdx.x;
    const int row0 = blockIdx.x * RPB;

    __shared__ float sh_xt[RPB];
    __shared__ float sh_m[8];
    __shared__ float sh_s[8];
    __shared__ float sh_M, sh_S;
    __shared__ int   sh_idx[8];

    // Resolve all target logits up front (dependent chain off the critical tail)
    if (tid < RPB) {
        int t = __ldg(y_true + row0 + tid);
        sh_xt[tid] = __ldg(y_pred + (size_t)(row0 + tid) * NCLS + t);
    }

    float4 buf[2][5];

    // Prefetch row 0
    {
        const float4* __restrict__ p =
            reinterpret_cast<const float4*>(y_pred + (size_t)row0 * NCLS);
        #pragma unroll
        for (int it = 0; it < 5; ++it) {
            int i = tid + it * BLK;
            if (it < 4 || i < NV4) buf[0][it] = __ldcs(p + i);
            else buf[0][it] = make_float4(-1e30f, -1e30f, -1e30f, -1e30f);
        }
    }

    const unsigned full = 0xffffffffu;
    const int wid = tid >> 5, lane = tid & 31;

    int   am[RPB];     // thread 0: per-level argmax (registers, r unrolled)
    float cel[RPB];    // thread 0: per-level cross-entropy

    #pragma unroll
    for (int r = 0; r < RPB; ++r) {
        float4* v = buf[r & 1];

        // ---- prefetch next row (loads fly across the barriers below) ----
        if (r + 1 < RPB) {
            const float4* __restrict__ pn =
                reinterpret_cast<const float4*>(y_pred + (size_t)(row0 + r + 1) * NCLS);
            float4* w = buf[(r + 1) & 1];
            #pragma unroll
            for (int it = 0; it < 5; ++it) {
                int i = tid + it * BLK;
                if (it < 4 || i < NV4) w[it] = __ldcs(pn + i);
                else w[it] = make_float4(-1e30f, -1e30f, -1e30f, -1e30f);
            }
        }

        // ---- Phase A: local max (pure FMNMX tree) ----
        float mloc = fmaxf(fmaxf(v[0].x, v[0].y), fmaxf(v[0].z, v[0].w));
        #pragma unroll
        for (int it = 1; it < 5; ++it)
            mloc = fmaxf(mloc, fmaxf(fmaxf(v[it].x, v[it].y),
                                     fmaxf(v[it].z, v[it].w)));

        // ---- Phase B: sum exp2(x*L2E - ml), 4 accumulators ----
        const float ml = mloc * L2E;
        float s0 = 0.f, s1 = 0.f, s2 = 0.f, s3 = 0.f;
        #pragma unroll
        for (int it = 0; it < 5; ++it) {
            s0 += ex2(fmaf(v[it].x, L2E, -ml));
            s1 += ex2(fmaf(v[it].y, L2E, -ml));
            s2 += ex2(fmaf(v[it].z, L2E, -ml));
            s3 += ex2(fmaf(v[it].w, L2E, -ml));
        }
        float s = (s0 + s1) + (s2 + s3);
        float m = mloc;

        // ---- warp reduce (m, s) ----
        #pragma unroll
        for (int off = 16; off; off >>= 1) {
            float om = __shfl_down_sync(full, m, off);
            float os = __shfl_down_sync(full, s, off);
            float nm = fmaxf(m, om);
            s = s * ex2((m - nm) * L2E) + os * ex2((om - nm) * L2E);
            m = nm;
        }
        if (lane == 0) { sh_m[wid] = m; sh_s[wid] = s; }
        __syncthreads();

        if (wid == 0) {
            m = (lane < 8) ? sh_m[lane] : -1e30f;
            s = (lane < 8) ? sh_s[lane] : 0.0f;
            #pragma unroll
            for (int off = 4; off; off >>= 1) {
                float om = __shfl_down_sync(full, m, off);
                float os = __shfl_down_sync(full, s, off);
                float nm = fmaxf(m, om);
                s = s * ex2((m - nm) * L2E) + os * ex2((om - nm) * L2E);
                m = nm;
            }
            if (lane == 0) { sh_M = m; sh_S = s; }
        }
        __syncthreads();

        // ---- argmax: equality rescan (signed INT_MAX sentinel — R6 lesson) ----
        const float M = sh_M;
        int idx = 0x7fffffff;
        if (mloc == M) {
            #pragma unroll
            for (int it = 0; it < 5; ++it) {
                int gi = (tid + it * BLK) << 2;
                if (v[it].x == M) idx = min(idx, gi + 0);
                if (v[it].y == M) idx = min(idx, gi + 1);
                if (v[it].z == M) idx = min(idx, gi + 2);
                if (v[it].w == M) idx = min(idx, gi + 3);
            }
        }
        idx = __reduce_min_sync(full, idx);
        if (lane == 0) sh_idx[wid] = idx;
        __syncthreads();

        if (tid == 0) {
            int best = sh_idx[0];
            #pragma unroll
            for (int w = 1; w < 8; ++w) best = min(best, sh_idx[w]);
            am[r]  = best;
            cel[r] = fmaf(LN2, __log2f(sh_S), sh_M) - sh_xt[r];
        }
    }

    // ---- fused epilogue: H consistency probes for this batch item ----
    if (tid == 0) {
        float h1 = __ldg(H + (size_t)am[0] * NCLS + am[1]);
        float h2 = __ldg(H + (size_t)am[1] * NCLS + am[2]);
        float h3 = __ldg(H + (size_t)am[2] * NCLS + am[3]);
        float c1 = (h1 != 1.0f) ? 1.0f : 0.0f;
        float c2 = (h2 != 1.0f) ? 1.0f : 0.0f;
        float c3 = (h3 != 1.0f) ? 1.0f : 0.0f;
        float pcw = 0.25f * c1 + 0.15f * c2 + 0.10f * c3;
        float pce = 0.25f * cel[1] + 0.15f * cel[2] + 0.10f * cel[3];
        g_part[blockIdx.x] = make_float2(pce, pcw);
    }

    // PDL: partial stored — allow the dependent reduce grid to launch.
#if __CUDA_ARCH__ >= 900
    cudaTriggerProgrammaticLaunchCompletion();
#endif
}

// ---------------------------------------------------------------------------
// Kernel 2: deterministic reduction of 4096 float2 partials -> scalar loss.
// Launched via PDL: ramps up concurrently with kernel 1, waits on the grid
// dependency, then does 2 x LDG.128 per thread + fixed-order tree reduce.
// ---------------------------------------------------------------------------
__global__ __launch_bounds__(1024)
void final_reduce_kernel(float* __restrict__ out)
{
#if __CUDA_ARCH__ >= 900
    cudaGridDependencySynchronize();
#endif

    const int tid = threadIdx.x;
    const float4* __restrict__ gp4 = reinterpret_cast<const float4*>(g_part);

    // 2048 float4 total; thread t takes gp4[t] and gp4[t + 1024].
    float4 a = gp4[tid];
    float4 b = gp4[tid + 1024];
    float ace = (a.x + a.z) + (b.x + b.z);   // .x/.z = pce of two partials
    float acw = (a.y + a.w) + (b.y + b.w);   // .y/.w = pcw of two partials

    const unsigned full = 0xffffffffu;
    #pragma unroll
    for (int off = 16; off; off >>= 1) {
        ace += __shfl_down_sync(full, ace, off);
        acw += __shfl_down_sync(full, acw, off);
    }

    __shared__ float s_ce[32], s_cw[32];
    const int wid = tid >> 5, lane = tid & 31;
    if (lane == 0) { s_ce[wid] = ace; s_cw[wid] = acw; }
    __syncthreads();

    if (wid == 0) {
        float tce = s_ce[lane];
        float tcw = s_cw[lane];
        #pragma unroll
        for (int off = 16; off; off >>= 1) {
            tce += __shfl_down_sync(full, tce, off);
            tcw += __shfl_down_sync(full, tcw, off);
        }
        if (lane == 0) {
            const float E  = 2.718281828459045f;
            const float iB = 1.0f / (float)NB;
            out[0] = E * tcw + tce * iB;
        }
    }
}

// ---------------------------------------------------------------------------
extern "C" void kernel_launch(void* const* d_in, const int* in_sizes, int n_in,
                              void* d_out, int out_size)
{
    const float* y_pred = nullptr;
    const int*   y_true = nullptr;
    const float* H      = nullptr;
    for (int i = 0; i < n_in; ++i) {
        if (in_sizes[i] == NROWS * NCLS)      y_pred = (const float*)d_in[i];
        else if (in_sizes[i] == NROWS)        y_true = (const int*)d_in[i];
        else if (in_sizes[i] == NCLS * NCLS)  H      = (const float*)d_in[i];
    }

    row_stats_kernel<<<GRID1, BLK>>>(y_pred, y_true, H);

    // Dependent launch of the reduce with programmatic stream serialization:
    // its launch/ramp overlaps with row_stats execution.
    cudaLaunchConfig_t cfg = {};
    cfg.gridDim  = dim3(1, 1, 1);
    cfg.blockDim = dim3(1024, 1, 1);
    cfg.dynamicSmemBytes = 0;
    cfg.stream = 0;
    cudaLaunchAttribute attr[1];
    attr[0].id = cudaLaunchAttributeProgrammaticStreamSerialization;
    attr[0].val.programmaticStreamSerializationAllowed = 1;
    cfg.attrs = attr;
    cfg.numAttrs = 1;
    cudaLaunchKernelEx(&cfg, final_reduce_kernel, (float*)d_out);
}